// round 2
// baseline (speedup 1.0000x reference)
#include <cuda_runtime.h>
#include <cuda_bf16.h>

// ---------------------------------------------------------------------------
// MAUCHLoss fused single-kernel version.
//   sig   = sigmoid(x)
//   cel_e = l*sig - softplus(sig)   (== l*log(s2) + (1-l)*log(1-s2), s2=sig(sig))
//   per col c: Ssig[c], Slsig[c], Sl[c]
//   penalty[c] = 1 - Slsig/npos + (Ssig-Slsig)/(B-npos)
//   out[0] = cel + 0.1*(sum(penalty)/15);  out[1] = 0.1*penalty[14]
// softplus(u), u in (0,1): ln2 + u/2 + w*(1/8 - w/192 + w^2/2880), w=u^2
//   -> per element accumulate only w*p(w); ln2 and u/2 fold into N and sum(sig).
//
// Reduction: per-block partials to g_scratch (deterministic order), then the
// last block to finish (fence + atomicInc) sums the partials and writes out.
// ---------------------------------------------------------------------------

#define NBLK   304
#define NTHR   256
#define NACC   46          // 15 Ssig + 15 Slsig + 15 Sl + 1 Swp

__device__ float        g_scratch[NACC * NBLK];
__device__ unsigned int g_count;        // zero-init; reset by last block

__device__ __forceinline__ float fast_ex2(float a) {
    float r; asm("ex2.approx.ftz.f32 %0, %1;" : "=f"(r) : "f"(a)); return r;
}
__device__ __forceinline__ float fast_rcp(float a) {
    float r; asm("rcp.approx.ftz.f32 %0, %1;" : "=f"(r) : "f"(a)); return r;
}

__device__ __forceinline__ void elem_update(float x, float lb, float* acc, int col) {
    const float NLOG2E = -1.4426950408889634f;
    float t   = fast_ex2(NLOG2E * x);       // e^{-x}
    float sig = fast_rcp(1.0f + t);         // sigmoid(x)
    float w   = sig * sig;
    float p   = fmaf(fmaf(3.4722222e-4f, w, -5.2083333e-3f), w, 0.125f);
    acc[col]      += sig;
    acc[15 + col]  = fmaf(lb, sig, acc[15 + col]);
    acc[30 + col] += lb;
    acc[45]        = fmaf(w, p, acc[45]);   // accumulate w*p(w)
}

__global__ __launch_bounds__(NTHR)
void mauc_fused(const float4* __restrict__ outp, const float4* __restrict__ labp,
                float* __restrict__ out, int n, int nchunk)
{
    float acc[NACC];
#pragma unroll
    for (int i = 0; i < NACC; i++) acc[i] = 0.0f;

    const int stride = gridDim.x * blockDim.x;
#pragma unroll 1
    for (int c = blockIdx.x * blockDim.x + threadIdx.x; c < nchunk; c += stride) {
        const float4* o = outp + (size_t)c * 15;
        const float4* l = labp + (size_t)c * 15;
#pragma unroll
        for (int i = 0; i < 15; i++) {
            float4 xo = o[i];
            float4 xl = l[i];
            elem_update(xo.x, xl.x, acc, (4 * i + 0) % 15);
            elem_update(xo.y, xl.y, acc, (4 * i + 1) % 15);
            elem_update(xo.z, xl.z, acc, (4 * i + 2) % 15);
            elem_update(xo.w, xl.w, acc, (4 * i + 3) % 15);
        }
    }

    // ---- block reduction: warp shfl, then per-warp rows via smem ----
    const unsigned FULL = 0xFFFFFFFFu;
#pragma unroll
    for (int v = 0; v < NACC; v++) {
        float s = acc[v];
        s += __shfl_down_sync(FULL, s, 16);
        s += __shfl_down_sync(FULL, s, 8);
        s += __shfl_down_sync(FULL, s, 4);
        s += __shfl_down_sync(FULL, s, 2);
        s += __shfl_down_sync(FULL, s, 1);
        acc[v] = s;
    }

    __shared__ float sm[NTHR / 32][NACC];
    const int wid  = threadIdx.x >> 5;
    const int lane = threadIdx.x & 31;
    if (lane == 0) {
#pragma unroll
        for (int v = 0; v < NACC; v++) sm[wid][v] = acc[v];
    }
    __syncthreads();
    if (threadIdx.x < NACC) {
        float s = 0.0f;
#pragma unroll
        for (int w = 0; w < NTHR / 32; w++) s += sm[w][threadIdx.x];
        g_scratch[threadIdx.x * NBLK + blockIdx.x] = s;
    }

    // ---- last-block-done: final reduction + scalar epilogue ----
    __shared__ bool is_last;
    __threadfence();
    __syncthreads();
    if (threadIdx.x == 0) {
        unsigned prev = atomicAdd(&g_count, 1u);
        is_last = (prev == gridDim.x - 1);
    }
    __syncthreads();
    if (!is_last) return;
    __threadfence();   // acquire: make all g_scratch writes visible

    __shared__ float tot[NACC];
    for (int v = wid; v < NACC; v += NTHR / 32) {
        float s = 0.0f;
        for (int b = lane; b < NBLK; b += 32) s += g_scratch[v * NBLK + b];
        s += __shfl_down_sync(FULL, s, 16);
        s += __shfl_down_sync(FULL, s, 8);
        s += __shfl_down_sync(FULL, s, 4);
        s += __shfl_down_sync(FULL, s, 2);
        s += __shfl_down_sync(FULL, s, 1);
        if (lane == 0) tot[v] = s;
    }
    __syncthreads();

    if (threadIdx.x == 0) {
        const double LN2 = 0.6931471805599453;
        double N  = (double)n;
        double Bf = N / 15.0;

        double sum_sig_all = 0.0, sum_lsig_all = 0.0;
        double sum_term = 0.0, pen14 = 0.0;
        for (int c = 0; c < 15; c++) {
            double ss = (double)tot[c];
            double sl = (double)tot[15 + c];
            double np = (double)tot[30 + c];
            sum_sig_all  += ss;
            sum_lsig_all += sl;
            double nn = Bf - np;
            double mp = (np > 0.0) ? sl / fmax(np, 1.0) : 0.0;
            double mn = (nn > 0.0) ? (ss - sl) / fmax(nn, 1.0) : 0.0;
            double pen = 1.0 - mp + mn;
            sum_term += pen;
            if (c == 14) pen14 = pen;
        }
        double swp = (double)tot[45];
        // sum softplus(sig) = N*ln2 + 0.5*sum(sig) + sum(w*p)
        double sp_total = N * LN2 + 0.5 * sum_sig_all + swp;
        double cel = (sp_total - sum_lsig_all) / N;
        out[0] = (float)(cel + 0.1 * (sum_term / 15.0));
        out[1] = (float)(0.1 * pen14);

        g_count = 0;   // reset for next (graph-replayed) launch
    }
}

extern "C" void kernel_launch(void* const* d_in, const int* in_sizes, int n_in,
                              void* d_out, int out_size)
{
    const float* outp = (const float*)d_in[0];
    const float* labp = (const float*)d_in[1];
    int n = in_sizes[0];
    int nchunk = n / 60;   // 60 floats (15 float4) per chunk; B*C = 31457280 divides evenly

    mauc_fused<<<NBLK, NTHR>>>((const float4*)outp, (const float4*)labp,
                               (float*)d_out, n, nchunk);
}

// round 3
// speedup vs baseline: 1.0299x; 1.0299x over previous
#include <cuda_runtime.h>
#include <cuda_bf16.h>

// ---------------------------------------------------------------------------
// MAUCHLoss fused single-kernel, depth-5 software-pipelined streaming version.
//   sig   = sigmoid(x)
//   cel_e = l*sig - softplus(sig)   (== l*log(s2) + (1-l)*log(1-s2), s2=sig(sig))
//   per col c: Ssig[c], Slsig[c], Sl[c]
//   penalty[c] = 1 - Slsig/npos + (Ssig-Slsig)/(B-npos)
//   out[0] = cel + 0.1*(sum(penalty)/15);  out[1] = 0.1*penalty[14]
// softplus(u), u in (0,1): ln2 + u/2 + w*(1/8 - w/192 + w^2/2880), w=u^2
//   -> per element accumulate only w*p(w); ln2 and u/2 fold into N and sum(sig).
//
// Each thread owns whole 60-element chunks (15 float4 per array) so the
// category index of every element is a compile-time constant. A 5-deep ring
// of (o,l) float4 pairs keeps ~10 LDG.128 in flight per warp; 5 | 15 makes the
// ring phase seamless across chunk boundaries.
// ---------------------------------------------------------------------------

#define NBLK   304
#define NTHR   256
#define NACC   46          // 15 Ssig + 15 Slsig + 15 Sl + 1 Swp
#define PD     5           // pipeline depth (must divide 15)

__device__ float        g_scratch[NACC * NBLK];
__device__ unsigned int g_count;        // zero-init; reset by last block

__device__ __forceinline__ float fast_ex2(float a) {
    float r; asm("ex2.approx.ftz.f32 %0, %1;" : "=f"(r) : "f"(a)); return r;
}
__device__ __forceinline__ float fast_rcp(float a) {
    float r; asm("rcp.approx.ftz.f32 %0, %1;" : "=f"(r) : "f"(a)); return r;
}

__device__ __forceinline__ void elem_update(float x, float lb, float* acc, int col) {
    const float NLOG2E = -1.4426950408889634f;
    float t   = fast_ex2(NLOG2E * x);       // e^{-x}
    float sig = fast_rcp(1.0f + t);         // sigmoid(x)
    float w   = sig * sig;
    float p   = fmaf(fmaf(3.4722222e-4f, w, -5.2083333e-3f), w, 0.125f);
    acc[col]      += sig;
    acc[15 + col]  = fmaf(lb, sig, acc[15 + col]);
    acc[30 + col] += lb;
    acc[45]        = fmaf(w, p, acc[45]);   // accumulate w*p(w)
}

__global__ __launch_bounds__(NTHR, 2)
void mauc_fused(const float4* __restrict__ outp, const float4* __restrict__ labp,
                float* __restrict__ out, int n, int nchunk)
{
    float acc[NACC];
#pragma unroll
    for (int i = 0; i < NACC; i++) acc[i] = 0.0f;

    const int stride = gridDim.x * blockDim.x;
    int c = blockIdx.x * blockDim.x + threadIdx.x;

    if (c < nchunk) {
        const float4* o = outp + (size_t)c * 15;
        const float4* l = labp + (size_t)c * 15;

        float4 po[PD], pl[PD];
#pragma unroll
        for (int k = 0; k < PD; k++) { po[k] = o[k]; pl[k] = l[k]; }

        while (c < nchunk) {
            const int  cn = c + stride;
            const bool hn = cn < nchunk;
            // if no next chunk, point at current (safe reads; values unused)
            const float4* no = outp + (size_t)(hn ? cn : c) * 15;
            const float4* nl = labp + (size_t)(hn ? cn : c) * 15;

#pragma unroll
            for (int i = 0; i < 15; i++) {
                float4 xo = po[i % PD];
                float4 xl = pl[i % PD];
                // prefetch element i+PD (slot (i+PD)%PD == i%PD; PD|15 keeps
                // phase consistent across the chunk boundary)
                if (i + PD < 15) {
                    po[i % PD] = o[i + PD];
                    pl[i % PD] = l[i + PD];
                } else {
                    po[i % PD] = no[i + PD - 15];
                    pl[i % PD] = nl[i + PD - 15];
                }
                elem_update(xo.x, xl.x, acc, (4 * i + 0) % 15);
                elem_update(xo.y, xl.y, acc, (4 * i + 1) % 15);
                elem_update(xo.z, xl.z, acc, (4 * i + 2) % 15);
                elem_update(xo.w, xl.w, acc, (4 * i + 3) % 15);
            }
            c = cn; o = no; l = nl;
        }
    }

    // ---- block reduction: warp shfl, then per-warp rows via smem ----
    const unsigned FULL = 0xFFFFFFFFu;
#pragma unroll
    for (int v = 0; v < NACC; v++) {
        float s = acc[v];
        s += __shfl_down_sync(FULL, s, 16);
        s += __shfl_down_sync(FULL, s, 8);
        s += __shfl_down_sync(FULL, s, 4);
        s += __shfl_down_sync(FULL, s, 2);
        s += __shfl_down_sync(FULL, s, 1);
        acc[v] = s;
    }

    __shared__ float sm[NTHR / 32][NACC];
    const int wid  = threadIdx.x >> 5;
    const int lane = threadIdx.x & 31;
    if (lane == 0) {
#pragma unroll
        for (int v = 0; v < NACC; v++) sm[wid][v] = acc[v];
    }
    __syncthreads();
    if (threadIdx.x < NACC) {
        float s = 0.0f;
#pragma unroll
        for (int w = 0; w < NTHR / 32; w++) s += sm[w][threadIdx.x];
        g_scratch[threadIdx.x * NBLK + blockIdx.x] = s;
    }

    // ---- last-block-done: final reduction + scalar epilogue ----
    __shared__ bool is_last;
    __threadfence();
    __syncthreads();
    if (threadIdx.x == 0) {
        unsigned prev = atomicAdd(&g_count, 1u);
        is_last = (prev == gridDim.x - 1);
    }
    __syncthreads();
    if (!is_last) return;
    __threadfence();   // acquire: make all g_scratch writes visible

    __shared__ float tot[NACC];
    for (int v = wid; v < NACC; v += NTHR / 32) {
        float s = 0.0f;
        for (int b = lane; b < NBLK; b += 32) s += g_scratch[v * NBLK + b];
        s += __shfl_down_sync(FULL, s, 16);
        s += __shfl_down_sync(FULL, s, 8);
        s += __shfl_down_sync(FULL, s, 4);
        s += __shfl_down_sync(FULL, s, 2);
        s += __shfl_down_sync(FULL, s, 1);
        if (lane == 0) tot[v] = s;
    }
    __syncthreads();

    if (threadIdx.x == 0) {
        const double LN2 = 0.6931471805599453;
        double N  = (double)n;
        double Bf = N / 15.0;

        double sum_sig_all = 0.0, sum_lsig_all = 0.0;
        double sum_term = 0.0, pen14 = 0.0;
        for (int cc = 0; cc < 15; cc++) {
            double ss = (double)tot[cc];
            double sl = (double)tot[15 + cc];
            double np = (double)tot[30 + cc];
            sum_sig_all  += ss;
            sum_lsig_all += sl;
            double nn = Bf - np;
            double mp = (np > 0.0) ? sl / fmax(np, 1.0) : 0.0;
            double mn = (nn > 0.0) ? (ss - sl) / fmax(nn, 1.0) : 0.0;
            double pen = 1.0 - mp + mn;
            sum_term += pen;
            if (cc == 14) pen14 = pen;
        }
        double swp = (double)tot[45];
        // sum softplus(sig) = N*ln2 + 0.5*sum(sig) + sum(w*p)
        double sp_total = N * LN2 + 0.5 * sum_sig_all + swp;
        double cel = (sp_total - sum_lsig_all) / N;
        out[0] = (float)(cel + 0.1 * (sum_term / 15.0));
        out[1] = (float)(0.1 * pen14);

        g_count = 0;   // reset for next (graph-replayed) launch
    }
}

extern "C" void kernel_launch(void* const* d_in, const int* in_sizes, int n_in,
                              void* d_out, int out_size)
{
    const float* outp = (const float*)d_in[0];
    const float* labp = (const float*)d_in[1];
    int n = in_sizes[0];
    int nchunk = n / 60;   // 60 floats (15 float4) per chunk; B*C divides evenly

    mauc_fused<<<NBLK, NTHR>>>((const float4*)outp, (const float4*)labp,
                               (float*)d_out, n, nchunk);
}